// round 3
// baseline (speedup 1.0000x reference)
#include <cuda_runtime.h>
#include <cstdint>
#include <math.h>

#define Bn 4
#define Hn 256
#define Wn 320
#define HWn (Hn*Wn)          // 81920
#define NPIX (Bn*HWn)        // 327680
#define NSn 256

// ---------------- scratch (device globals) -----------------------------------
__device__ float g_z [(size_t)NPIX*32];
__device__ float g_rh[(size_t)NPIX*32];
__device__ float g_t2[(size_t)64*NPIX];

// ---------------- helpers -----------------------------------------------------
__device__ __forceinline__ uint32_t f2tf(float v){
    uint32_t u; asm("cvt.rna.tf32.f32 %0, %1;" : "=r"(u) : "f"(v));
    return u;
}
__device__ __forceinline__ void mma8(float4& d,
    uint32_t a0, uint32_t a1, uint32_t a2, uint32_t a3,
    uint32_t b0, uint32_t b1){
    asm volatile("mma.sync.aligned.m16n8k8.row.col.f32.tf32.tf32.f32 "
        "{%0,%1,%2,%3},{%4,%5,%6,%7},{%8,%9},{%0,%1,%2,%3};"
        : "+f"(d.x), "+f"(d.y), "+f"(d.z), "+f"(d.w)
        : "r"(a0), "r"(a1), "r"(a2), "r"(a3), "r"(b0), "r"(b1));
}
__device__ __forceinline__ float sigmoidf_(float v){ return 1.f/(1.f+__expf(-v)); }

// ---------------- implicit-GEMM conv via mma.sync tf32x3 ----------------------
// MODE 0: zr  — in 65ch dil1, N=64 (z|r)   -> g_z, g_rh
// MODE 1: q   — in 65ch dil1, N=32         -> h
// MODE 2: hd  — in 32ch dil2, N=64 (dh1|ch1) + dh2 + conf -> g_t2, conf, conf0
template<int MODE>
__global__ void __launch_bounds__(128) conv_mma(
    const float* __restrict__ in0,
    const float* __restrict__ ndep,
    const float* __restrict__ corr,
    const float* __restrict__ wA,
    const float* __restrict__ wB,
    const float* __restrict__ biasA,
    const float* __restrict__ biasB,
    const float* __restrict__ hidden,
    const float* __restrict__ zbuf,
    const float* __restrict__ dh2w,
    const float* __restrict__ ch2w,
    const float* __restrict__ ch2b,
    float* __restrict__ o0,
    float* __restrict__ o1,
    float* __restrict__ o2)
{
    constexpr int N    = (MODE == 1) ? 32 : 64;
    constexpr int NT   = N / 8;
    constexpr int NCH  = (MODE == 2) ? 32 : 65;
    constexpr int KTOT = NCH * 9;                 // 585 or 288
    constexpr int NCHK = (KTOT + 31) / 32;        // 19 or 9
    constexpr int DIL  = (MODE == 2) ? 2 : 1;

    extern __shared__ float sm[];
    uint32_t* AhU = (uint32_t*)sm;                // [128][36] tf32 hi
    uint32_t* AlU = AhU + 128*36;                 // [128][36] tf32 lo
    uint32_t* BhU = AlU + 128*36;                 // [N][36]
    uint32_t* BlU = BhU + N*36;
    float*    bias_s = (float*)(BlU + N*36);      // [64]
    float*    extra  = bias_s + 64;               // MODE2: dh2w [ic][64] = 2048
    float*    A1     = (float*)AhU;               // MODE2 overlay: [128][33]

    int tid  = threadIdx.x;
    int lane = tid & 31;
    int w    = tid >> 5;
    int r    = lane >> 2;       // fragment group row
    int cq   = lane & 3;        // fragment group col

    if (MODE == 0){
        if (tid < 32)       bias_s[tid] = biasA[tid];
        else if (tid < 64)  bias_s[tid] = biasB[tid-32];
    } else if (MODE == 1){
        if (tid < 32) bias_s[tid] = biasA[tid];
    } else {
        for (int e = tid; e < 2048; e += 128){
            int ic = e >> 6, oc = e & 63;
            extra[e] = dh2w[oc*32 + ic];
        }
        if (tid < 32) bias_s[tid] = ch2w[tid];
    }

    int gp0 = blockIdx.x * 128;
    int b   = gp0 / HWn;               // whole CTA in one batch (128 | HWn)
    int hwb = gp0 - b*HWn;
    int hw  = hwb + tid;
    int y   = hw / Wn;
    int x   = hw - y*Wn;

    float4 acc[2][NT];
    #pragma unroll
    for (int mt = 0; mt < 2; ++mt)
        #pragma unroll
        for (int nt = 0; nt < NT; ++nt)
            acc[mt][nt] = make_float4(0.f, 0.f, 0.f, 0.f);

    for (int c = 0; c < NCHK; ++c){
        __syncthreads();   // previous chunk's mma done reading before overwrite

        // ---- stage A (im2col for this thread's pixel), 32 k values ----
        #pragma unroll
        for (int k4 = 0; k4 < 8; ++k4){
            uint32_t hv[4], lv[4];
            #pragma unroll
            for (int t = 0; t < 4; ++t){
                int kk = c*32 + k4*4 + t;
                float val = 0.f;
                if (kk < KTOT){
                    int ic = kk / 9; int j = kk - ic*9;
                    int j3 = j / 3;
                    int dy = j3 - 1, dx = j - j3*3 - 1;
                    int yy = y + dy*DIL, xx = x + dx*DIL;
                    if (yy >= 0 && yy < Hn && xx >= 0 && xx < Wn){
                        const float* s;
                        if (ic < 32)       s = in0  + ((size_t)(b*32 + ic))*HWn;
                        else if (ic == 32) s = ndep + (size_t)b*HWn;
                        else               s = corr + ((size_t)(b*32 + ic - 33))*HWn;
                        val = __ldg(s + yy*Wn + xx);
                    }
                }
                uint32_t hb = f2tf(val);
                hv[t] = hb;
                lv[t] = f2tf(val - __uint_as_float(hb));
            }
            *(uint4*)(AhU + tid*36 + k4*4) = make_uint4(hv[0], hv[1], hv[2], hv[3]);
            *(uint4*)(AlU + tid*36 + k4*4) = make_uint4(lv[0], lv[1], lv[2], lv[3]);
        }

        // ---- stage B (weights), rows = out channels ----
        #pragma unroll
        for (int e = tid; e < N*8; e += 128){
            int n = e >> 3, k4 = e & 7;
            const float* ws = (MODE == 1) ? (wA + n*KTOT)
                            : (n < 32 ? wA + n*KTOT : wB + (n-32)*KTOT);
            uint32_t hv[4], lv[4];
            #pragma unroll
            for (int t = 0; t < 4; ++t){
                int kk = c*32 + k4*4 + t;
                float val = (kk < KTOT) ? __ldg(ws + kk) : 0.f;
                uint32_t hb = f2tf(val);
                hv[t] = hb;
                lv[t] = f2tf(val - __uint_as_float(hb));
            }
            *(uint4*)(BhU + n*36 + k4*4) = make_uint4(hv[0], hv[1], hv[2], hv[3]);
            *(uint4*)(BlU + n*36 + k4*4) = make_uint4(lv[0], lv[1], lv[2], lv[3]);
        }

        __syncthreads();

        // ---- 4 k-steps of 8 ----
        #pragma unroll
        for (int ks = 0; ks < 4; ++ks){
            int k0 = ks*8;
            uint32_t ah[2][4], al[2][4];
            #pragma unroll
            for (int mt = 0; mt < 2; ++mt){
                int R = (w*32 + mt*16 + r)*36 + k0 + cq;
                ah[mt][0] = AhU[R];
                ah[mt][1] = AhU[R + 8*36];
                ah[mt][2] = AhU[R + 4];
                ah[mt][3] = AhU[R + 8*36 + 4];
                al[mt][0] = AlU[R];
                al[mt][1] = AlU[R + 8*36];
                al[mt][2] = AlU[R + 4];
                al[mt][3] = AlU[R + 8*36 + 4];
            }
            #pragma unroll
            for (int nt = 0; nt < NT; ++nt){
                int Bi = (nt*8 + r)*36 + k0 + cq;
                uint32_t b0h = BhU[Bi], b1h = BhU[Bi + 4];
                uint32_t b0l = BlU[Bi], b1l = BlU[Bi + 4];
                #pragma unroll
                for (int mt = 0; mt < 2; ++mt){
                    mma8(acc[mt][nt], ah[mt][0], ah[mt][1], ah[mt][2], ah[mt][3], b0h, b1h);
                    mma8(acc[mt][nt], ah[mt][0], ah[mt][1], ah[mt][2], ah[mt][3], b0l, b1l);
                    mma8(acc[mt][nt], al[mt][0], al[mt][1], al[mt][2], al[mt][3], b0h, b1h);
                }
            }
        }
    }

    // ---------------- epilogues ----------------
    if (MODE == 0){
        #pragma unroll
        for (int mt = 0; mt < 2; ++mt)
        #pragma unroll
        for (int half = 0; half < 2; ++half){
            int pl  = w*32 + mt*16 + r + 8*half;
            int hwp = hwb + pl;
            #pragma unroll
            for (int nt = 0; nt < NT; ++nt){
                int col0 = nt*8 + cq*2;
                float v0 = half ? acc[mt][nt].z : acc[mt][nt].x;
                float v1 = half ? acc[mt][nt].w : acc[mt][nt].y;
                if (nt < 4){
                    o0[((size_t)(b*32 + col0  ))*HWn + hwp] = sigmoidf_(v0 + bias_s[col0]);
                    o0[((size_t)(b*32 + col0+1))*HWn + hwp] = sigmoidf_(v1 + bias_s[col0+1]);
                } else {
                    size_t i0 = ((size_t)(b*32 + col0-32))*HWn + hwp;
                    size_t i1 = ((size_t)(b*32 + col0-31))*HWn + hwp;
                    o1[i0] = sigmoidf_(v0 + bias_s[col0])   * __ldg(hidden + i0);
                    o1[i1] = sigmoidf_(v1 + bias_s[col0+1]) * __ldg(hidden + i1);
                }
            }
        }
    } else if (MODE == 1){
        #pragma unroll
        for (int mt = 0; mt < 2; ++mt)
        #pragma unroll
        for (int half = 0; half < 2; ++half){
            int pl  = w*32 + mt*16 + r + 8*half;
            int hwp = hwb + pl;
            #pragma unroll
            for (int nt = 0; nt < NT; ++nt){
                int col0 = nt*8 + cq*2;
                float v0 = half ? acc[mt][nt].z : acc[mt][nt].x;
                float v1 = half ? acc[mt][nt].w : acc[mt][nt].y;
                float q0 = tanhf(v0 + bias_s[col0]);
                float q1 = tanhf(v1 + bias_s[col0+1]);
                size_t i0 = ((size_t)(b*32 + col0  ))*HWn + hwp;
                size_t i1 = ((size_t)(b*32 + col0+1))*HWn + hwp;
                float z0 = __ldg(zbuf + i0), z1 = __ldg(zbuf + i1);
                o0[i0] = (1.f - z0)*__ldg(hidden + i0) + z0*q0;
                o0[i1] = (1.f - z1)*__ldg(hidden + i1) + z1*q1;
            }
        }
    } else {
        float cb = __ldg(ch2b);
        __syncthreads();    // all warps done reading A smem before overlay
        float ps[2][2] = {{0.f,0.f},{0.f,0.f}};
        #pragma unroll
        for (int mt = 0; mt < 2; ++mt)
        #pragma unroll
        for (int half = 0; half < 2; ++half){
            int pl = w*32 + mt*16 + r + 8*half;
            #pragma unroll
            for (int nt = 0; nt < NT; ++nt){
                int col0 = nt*8 + cq*2;
                float v0 = half ? acc[mt][nt].z : acc[mt][nt].x;
                float v1 = half ? acc[mt][nt].w : acc[mt][nt].y;
                v0 = fmaxf(v0, 0.f);
                v1 = fmaxf(v1, 0.f);
                if (nt < 4){                     // dh1 output -> A1 smem
                    A1[pl*33 + col0  ] = v0;
                    A1[pl*33 + col0+1] = v1;
                } else {                         // ch1 output -> conf partial
                    ps[mt][half] = fmaf(v0, bias_s[col0-32],
                                   fmaf(v1, bias_s[col0-31], ps[mt][half]));
                }
            }
        }
        #pragma unroll
        for (int mt = 0; mt < 2; ++mt)
        #pragma unroll
        for (int half = 0; half < 2; ++half){
            float p = ps[mt][half];
            p += __shfl_xor_sync(0xffffffffu, p, 1);
            p += __shfl_xor_sync(0xffffffffu, p, 2);
            if (cq == 0){
                int pl = w*32 + mt*16 + r + 8*half;
                int g  = gp0 + pl;
                float cs = cb + p;
                o2[g] = cs;
                o1[g] = sigmoidf_(cs);
            }
        }
        __syncthreads();
        // dh2: 1x1 32->64, per-thread pixel
        float a[32];
        #pragma unroll
        for (int ic = 0; ic < 32; ++ic) a[ic] = A1[tid*33 + ic];
        float t2[64];
        #pragma unroll
        for (int i = 0; i < 64; ++i) t2[i] = 0.f;
        #pragma unroll
        for (int ic = 0; ic < 32; ++ic){
            float vv = a[ic];
            const float4* wr = (const float4*)(extra + ic*64);
            #pragma unroll
            for (int q4 = 0; q4 < 16; ++q4){
                float4 w4 = wr[q4];
                t2[q4*4+0] = fmaf(vv, w4.x, t2[q4*4+0]);
                t2[q4*4+1] = fmaf(vv, w4.y, t2[q4*4+1]);
                t2[q4*4+2] = fmaf(vv, w4.z, t2[q4*4+2]);
                t2[q4*4+3] = fmaf(vv, w4.w, t2[q4*4+3]);
            }
        }
        int g = gp0 + tid;
        #pragma unroll
        for (int oc = 0; oc < 64; ++oc)
            o0[(size_t)oc*NPIX + g] = fmaxf(t2[oc], 0.f);
    }
}

// ---------------- logits (64->256) + softmax + windowed depth regression -----
__global__ void softmax_head(const float* __restrict__ t2g,
                             const float* __restrict__ w3,
                             const float* __restrict__ b3,
                             float* __restrict__ prob,
                             float* __restrict__ nd)
{
    extern __shared__ float smem[];
    float* w3_s = smem;                   // 256*64
    float* t2_s = w3_s + 256*64;          // [32][65]
    float* b3_s = t2_s + 32*65;           // 256
    float* redA = b3_s + 256;             // [8][33]
    float* redB = redA + 8*33;
    int*   redI = (int*)(redB + 8*33);

    int tid = threadIdx.x;
    for (int i = tid; i < 256*64/4; i += blockDim.x)
        reinterpret_cast<float4*>(w3_s)[i] = reinterpret_cast<const float4*>(w3)[i];
    if (tid < 256) b3_s[tid] = b3[tid];

    int g0 = blockIdx.x * 32;
    #pragma unroll
    for (int i = 0; i < 8; i++) {
        int idx = tid + i*256;
        int k = idx >> 5; int l = idx & 31;
        t2_s[l*65 + k] = t2g[(size_t)k*NPIX + g0 + l];
    }
    __syncthreads();

    int w = tid >> 5;
    int l = tid & 31;
    int g = g0 + l;
    int b  = g / HWn;
    int hw = g - b*HWn;

    const float* t2r = t2_s + l*65;
    float lg[32];
    float lmax = -3.4e38f; int lamax = 0;
    #pragma unroll
    for (int j = 0; j < 32; j++) {
        int oc = w*32 + j;
        float acc = b3_s[oc];
        const float* wrow = w3_s + oc*64;
        #pragma unroll
        for (int k4 = 0; k4 < 16; k4++) {
            float4 wv = *reinterpret_cast<const float4*>(wrow + k4*4);
            acc = fmaf(t2r[k4*4+0], wv.x, acc);
            acc = fmaf(t2r[k4*4+1], wv.y, acc);
            acc = fmaf(t2r[k4*4+2], wv.z, acc);
            acc = fmaf(t2r[k4*4+3], wv.w, acc);
        }
        lg[j] = acc;
        if (acc > lmax) { lmax = acc; lamax = oc; }
    }

    redA[w*33 + l] = lmax; redI[w*33 + l] = lamax;
    __syncthreads();
    float M = -3.4e38f; int A = 0;
    #pragma unroll
    for (int ww = 0; ww < 8; ww++) {
        float m = redA[ww*33 + l];
        if (m > M) { M = m; A = redI[ww*33 + l]; }
    }

    float s = 0.f;
    #pragma unroll
    for (int j = 0; j < 32; j++) { lg[j] = __expf(lg[j] - M); s += lg[j]; }
    __syncthreads();
    redA[w*33 + l] = s;
    __syncthreads();
    float S = 0.f;
    #pragma unroll
    for (int ww = 0; ww < 8; ww++) S += redA[ww*33 + l];
    float rS = 1.f / S;

    int lo = A - 4, hi = A + 4;
    int ocl = lo < 0 ? 0 : lo;
    int och = hi > 255 ? 255 : hi;
    float num = 0.f, den = 0.f;
    #pragma unroll
    for (int j = 0; j < 32; j++) {
        int oc = w*32 + j;
        if (oc >= ocl && oc <= och) {
            float mult = 1.f;
            if (oc == 0   && lo < 0)   mult += (float)(-lo);
            if (oc == 255 && hi > 255) mult += (float)(hi - 255);
            float pv = lg[j] * rS;
            num = fmaf(mult * (float)oc, pv, num);
            den = fmaf(mult, pv, den);
        }
    }
    __syncthreads();
    redA[w*33 + l] = num; redB[w*33 + l] = den;
    __syncthreads();
    if (w == 0) {
        float Nv = 0.f, D = 0.f;
        #pragma unroll
        for (int ww = 0; ww < 8; ww++) { Nv += redA[ww*33 + l]; D += redB[ww*33 + l]; }
        nd[g] = (Nv / (1e-6f + D)) * (1.0f / 255.0f);
    }

    float* pbase = prob + (size_t)b*NSn*HWn + hw;
    #pragma unroll
    for (int j = 0; j < 32; j++)
        pbase[(size_t)(w*32 + j)*HWn] = lg[j] * rS;
}

// ---------------- launch ------------------------------------------------------
extern "C" void kernel_launch(void* const* d_in, const int* in_sizes, int n_in,
                              void* d_out, int out_size)
{
    const float* hidden  = (const float*)d_in[0];
    const float* ndep    = (const float*)d_in[1];
    const float* corr    = (const float*)d_in[2];
    const float* convz_w = (const float*)d_in[3];
    const float* convz_b = (const float*)d_in[4];
    const float* convr_w = (const float*)d_in[5];
    const float* convr_b = (const float*)d_in[6];
    const float* convq_w = (const float*)d_in[7];
    const float* convq_b = (const float*)d_in[8];
    const float* dh1_w   = (const float*)d_in[9];
    const float* dh2_w   = (const float*)d_in[10];
    const float* dh3_w   = (const float*)d_in[11];
    const float* dh3_b   = (const float*)d_in[12];
    const float* ch1_w   = (const float*)d_in[13];
    const float* ch2_w   = (const float*)d_in[14];
    const float* ch2_b   = (const float*)d_in[15];

    float* out = (float*)d_out;
    float* out_h     = out;
    float* out_nd    = out_h  + (size_t)NPIX*32;
    float* out_prob  = out_nd + NPIX;
    float* out_conf  = out_prob + (size_t)NPIX*256;
    float* out_conf0 = out_conf + NPIX;

    float* zbuf;  cudaGetSymbolAddress((void**)&zbuf,  g_z);
    float* rhbuf; cudaGetSymbolAddress((void**)&rhbuf, g_rh);
    float* t2buf; cudaGetSymbolAddress((void**)&t2buf, g_t2);

    const int SMEM_M0 = (128*36*2 + 64*36*2 + 64) * 4;          // 55552
    const int SMEM_M1 = (128*36*2 + 32*36*2 + 64) * 4;          // 46336
    const int SMEM_M2 = (128*36*2 + 64*36*2 + 64 + 2048) * 4;   // 63744
    const int SMEM_SMAX = (256*64 + 32*65 + 256 + 3*8*33)*4;

    cudaFuncSetAttribute(conv_mma<0>, cudaFuncAttributeMaxDynamicSharedMemorySize, SMEM_M0);
    cudaFuncSetAttribute(conv_mma<1>, cudaFuncAttributeMaxDynamicSharedMemorySize, SMEM_M1);
    cudaFuncSetAttribute(conv_mma<2>, cudaFuncAttributeMaxDynamicSharedMemorySize, SMEM_M2);
    cudaFuncSetAttribute(softmax_head, cudaFuncAttributeMaxDynamicSharedMemorySize, SMEM_SMAX);

    dim3 blk(128);
    dim3 grd(NPIX / 128);   // 2560

    conv_mma<0><<<grd, blk, SMEM_M0>>>(hidden, ndep, corr, convz_w, convr_w,
                                       convz_b, convr_b, hidden, nullptr,
                                       nullptr, nullptr, nullptr,
                                       zbuf, rhbuf, nullptr);
    conv_mma<1><<<grd, blk, SMEM_M1>>>(rhbuf, ndep, corr, convq_w, nullptr,
                                       convq_b, nullptr, hidden, zbuf,
                                       nullptr, nullptr, nullptr,
                                       out_h, nullptr, nullptr);
    conv_mma<2><<<grd, blk, SMEM_M2>>>(out_h, nullptr, nullptr, dh1_w, ch1_w,
                                       nullptr, nullptr, nullptr, nullptr,
                                       dh2_w, ch2_w, ch2_b,
                                       t2buf, out_conf, out_conf0);
    softmax_head<<<NPIX / 32, 256, SMEM_SMAX>>>(t2buf, dh3_w, dh3_b,
                                                out_prob, out_nd);
}

// round 4
// speedup vs baseline: 1.0597x; 1.0597x over previous
#include <cuda_runtime.h>
#include <cuda_fp16.h>
#include <cstdint>
#include <math.h>

#define Bn 4
#define Hn 256
#define Wn 320
#define HWn (Hn*Wn)          // 81920
#define NPIX (Bn*HWn)        // 327680
#define NSn 256

// ---------------- scratch (device globals) -----------------------------------
__device__ float g_z [(size_t)NPIX*32];
__device__ float g_rh[(size_t)NPIX*32];
__device__ float g_t2[(size_t)64*NPIX];

// ---------------- helpers -----------------------------------------------------
__device__ __forceinline__ uint32_t smem_u32(const void* p){
    uint32_t a;
    asm("{ .reg .u64 t; cvta.to.shared.u64 t, %1; cvt.u32.u64 %0, t; }" : "=r"(a) : "l"(p));
    return a;
}
__device__ __forceinline__ void ldm_x4(uint32_t* r, uint32_t addr){
    asm volatile("ldmatrix.sync.aligned.m8n8.x4.shared.b16 {%0,%1,%2,%3}, [%4];"
        : "=r"(r[0]), "=r"(r[1]), "=r"(r[2]), "=r"(r[3]) : "r"(addr));
}
__device__ __forceinline__ void mma16(float4& d, const uint32_t* a, uint32_t b0, uint32_t b1){
    asm volatile("mma.sync.aligned.m16n8k16.row.col.f32.f16.f16.f32 "
        "{%0,%1,%2,%3},{%4,%5,%6,%7},{%8,%9},{%0,%1,%2,%3};"
        : "+f"(d.x), "+f"(d.y), "+f"(d.z), "+f"(d.w)
        : "r"(a[0]), "r"(a[1]), "r"(a[2]), "r"(a[3]), "r"(b0), "r"(b1));
}
__device__ __forceinline__ float sigmoidf_(float v){ return 1.f/(1.f+__expf(-v)); }
// SW128 swizzle, 16B granularity: row-major 8-row cores of 128B rows
__device__ __forceinline__ uint32_t swzb(int row, int c16){
    return ((uint32_t)(row >> 3) << 10) | ((uint32_t)(row & 7) << 7)
         | ((uint32_t)((c16 ^ (row & 7)) & 7) << 4);
}

// ---------------- implicit-GEMM conv via mma.sync fp16x3 + ldmatrix ----------
// MODE 0: zr  — in 65ch dil1, N=64 (z|r)   -> g_z, g_rh
// MODE 1: q   — in 65ch dil1, N=32         -> h
// MODE 2: hd  — in 32ch dil2, N=64 (dh1|ch1) + dh2 + conf -> g_t2, conf, conf0
template<int MODE>
__global__ void __launch_bounds__(128) conv_mma(
    const float* __restrict__ in0,
    const float* __restrict__ ndep,
    const float* __restrict__ corr,
    const float* __restrict__ wA,
    const float* __restrict__ wB,
    const float* __restrict__ biasA,
    const float* __restrict__ biasB,
    const float* __restrict__ hidden,
    const float* __restrict__ zbuf,
    const float* __restrict__ dh2w,
    const float* __restrict__ ch2w,
    const float* __restrict__ ch2b,
    float* __restrict__ o0,
    float* __restrict__ o1,
    float* __restrict__ o2)
{
    constexpr int N    = (MODE == 1) ? 32 : 64;
    constexpr int NT   = N / 8;
    constexpr int NTP  = N / 16;
    constexpr int NCH  = (MODE == 2) ? 32 : 65;
    constexpr int KTOT = NCH * 9;                       // 585 or 288
    constexpr int NCHK = (KTOT + 63) / 64;              // 10 or 5
    constexpr int DIL  = (MODE == 2) ? 2 : 1;

    extern __shared__ char sm[];
    char* Ah = sm;                       // 128 x 128B (swizzled) fp16 hi
    char* Al = sm + 16384;               // fp16 lo
    char* Bh = sm + 32768;               // N x 128B
    char* Bl = Bh + N*128;
    float* bias_s = (float*)(Bl + N*128);      // [64]
    float* extra  = bias_s + 64;               // MODE2: dh2w [ic][64]
    float* A1     = (float*)Ah;                // MODE2 overlay [128][33]

    uint32_t AhS = smem_u32(Ah);
    uint32_t AlS = smem_u32(Al);
    uint32_t BhS = smem_u32(Bh);
    uint32_t BlS = smem_u32(Bl);

    int tid  = threadIdx.x;
    int lane = tid & 31;
    int w    = tid >> 5;
    int r    = lane >> 2;
    int cq   = lane & 3;

    if (MODE == 0){
        if (tid < 32)      bias_s[tid] = biasA[tid];
        else if (tid < 64) bias_s[tid] = biasB[tid-32];
    } else if (MODE == 1){
        if (tid < 32) bias_s[tid] = biasA[tid];
    } else {
        for (int e = tid; e < 2048; e += 128){
            int ic = e >> 6, oc = e & 63;
            extra[e] = dh2w[oc*32 + ic];
        }
        if (tid < 32) bias_s[tid] = ch2w[tid];
    }

    int gp0 = blockIdx.x * 128;
    int b   = gp0 / HWn;
    int hwb = gp0 - b*HWn;
    int hw  = hwb + tid;
    int y   = hw / Wn;
    int x   = hw - y*Wn;

    auto gatherA = [&](int kk) -> float {
        if (kk >= KTOT) return 0.f;
        int ic = kk / 9; int j = kk - ic*9;
        int j3 = j / 3;
        int dy = j3 - 1, dx = j - j3*3 - 1;
        int yy = y + dy*DIL, xx = x + dx*DIL;
        if (yy < 0 || yy >= Hn || xx < 0 || xx >= Wn) return 0.f;
        const float* s;
        if (MODE == 2)     s = in0  + ((size_t)(b*32 + ic))*HWn;
        else if (ic < 32)  s = in0  + ((size_t)(b*32 + ic))*HWn;
        else if (ic == 32) s = ndep + (size_t)b*HWn;
        else               s = corr + ((size_t)(b*32 + ic - 33))*HWn;
        return __ldg(s + yy*Wn + xx);
    };

    float4 acc[2][NT];
    #pragma unroll
    for (int mt = 0; mt < 2; ++mt)
        #pragma unroll
        for (int nt = 0; nt < NT; ++nt)
            acc[mt][nt] = make_float4(0.f, 0.f, 0.f, 0.f);

    for (int c = 0; c < NCHK; ++c){
        __syncthreads();   // previous chunk fully consumed

        // ---- stage A: this thread's pixel row, 64 k values ----
        #pragma unroll
        for (int c16 = 0; c16 < 8; ++c16){
            uint32_t hu[4], lu[4];
            #pragma unroll
            for (int p = 0; p < 4; ++p){
                float v0 = gatherA(c*64 + c16*8 + p*2);
                float v1 = gatherA(c*64 + c16*8 + p*2 + 1);
                __half h0 = __float2half_rn(v0), h1 = __float2half_rn(v1);
                __half l0 = __float2half_rn(v0 - __half2float(h0));
                __half l1 = __float2half_rn(v1 - __half2float(h1));
                hu[p] = (uint32_t)__half_as_ushort(h0) | ((uint32_t)__half_as_ushort(h1) << 16);
                lu[p] = (uint32_t)__half_as_ushort(l0) | ((uint32_t)__half_as_ushort(l1) << 16);
            }
            uint32_t off = swzb(tid, c16);
            *(uint4*)(Ah + off) = make_uint4(hu[0], hu[1], hu[2], hu[3]);
            *(uint4*)(Al + off) = make_uint4(lu[0], lu[1], lu[2], lu[3]);
        }

        // ---- stage B: weight rows ----
        #pragma unroll
        for (int e = tid; e < N*8; e += 128){
            int n = e >> 3, c16 = e & 7;
            const float* ws = (MODE == 1) ? (wA + n*KTOT)
                            : (n < 32 ? wA + n*KTOT : wB + (n-32)*KTOT);
            uint32_t hu[4], lu[4];
            #pragma unroll
            for (int p = 0; p < 4; ++p){
                int k0 = c*64 + c16*8 + p*2;
                float v0 = (k0     < KTOT) ? __ldg(ws + k0)     : 0.f;
                float v1 = (k0 + 1 < KTOT) ? __ldg(ws + k0 + 1) : 0.f;
                __half h0 = __float2half_rn(v0), h1 = __float2half_rn(v1);
                __half l0 = __float2half_rn(v0 - __half2float(h0));
                __half l1 = __float2half_rn(v1 - __half2float(h1));
                hu[p] = (uint32_t)__half_as_ushort(h0) | ((uint32_t)__half_as_ushort(h1) << 16);
                lu[p] = (uint32_t)__half_as_ushort(l0) | ((uint32_t)__half_as_ushort(l1) << 16);
            }
            uint32_t off = swzb(n, c16);
            *(uint4*)(Bh + off) = make_uint4(hu[0], hu[1], hu[2], hu[3]);
            *(uint4*)(Bl + off) = make_uint4(lu[0], lu[1], lu[2], lu[3]);
        }

        __syncthreads();

        // ---- 4 k16 steps ----
        #pragma unroll
        for (int ks = 0; ks < 4; ++ks){
            uint32_t ah[2][4], al[2][4];
            #pragma unroll
            for (int mt = 0; mt < 2; ++mt){
                int rowA = w*32 + mt*16 + (lane & 15);
                uint32_t off = ((uint32_t)(rowA >> 3) << 10) | ((uint32_t)(rowA & 7) << 7)
                             | ((uint32_t)(((ks*2 + (lane >> 4)) ^ (rowA & 7)) & 7) << 4);
                ldm_x4(ah[mt], AhS + off);
                ldm_x4(al[mt], AlS + off);
            }
            #pragma unroll
            for (int ntp = 0; ntp < NTP; ++ntp){
                int rowB = ntp*16 + (lane & 7) + ((lane >> 4) << 3);
                uint32_t off = ((uint32_t)(rowB >> 3) << 10) | ((uint32_t)(rowB & 7) << 7)
                             | ((uint32_t)(((ks*2 + ((lane >> 3) & 1)) ^ (rowB & 7)) & 7) << 4);
                uint32_t bh[4], bl[4];
                ldm_x4(bh, BhS + off);
                ldm_x4(bl, BlS + off);
                #pragma unroll
                for (int mt = 0; mt < 2; ++mt){
                    mma16(acc[mt][ntp*2  ], ah[mt], bh[0], bh[1]);
                    mma16(acc[mt][ntp*2  ], ah[mt], bl[0], bl[1]);
                    mma16(acc[mt][ntp*2  ], al[mt], bh[0], bh[1]);
                    mma16(acc[mt][ntp*2+1], ah[mt], bh[2], bh[3]);
                    mma16(acc[mt][ntp*2+1], ah[mt], bl[2], bl[3]);
                    mma16(acc[mt][ntp*2+1], al[mt], bh[2], bh[3]);
                }
            }
        }
    }

    // ---------------- epilogues ----------------
    if (MODE == 0){
        #pragma unroll
        for (int mt = 0; mt < 2; ++mt)
        #pragma unroll
        for (int half = 0; half < 2; ++half){
            int pl  = w*32 + mt*16 + r + 8*half;
            int hwp = hwb + pl;
            #pragma unroll
            for (int nt = 0; nt < NT; ++nt){
                int col0 = nt*8 + cq*2;
                float v0 = half ? acc[mt][nt].z : acc[mt][nt].x;
                float v1 = half ? acc[mt][nt].w : acc[mt][nt].y;
                if (nt < 4){
                    o0[((size_t)(b*32 + col0  ))*HWn + hwp] = sigmoidf_(v0 + bias_s[col0]);
                    o0[((size_t)(b*32 + col0+1))*HWn + hwp] = sigmoidf_(v1 + bias_s[col0+1]);
                } else {
                    size_t i0 = ((size_t)(b*32 + col0-32))*HWn + hwp;
                    size_t i1 = ((size_t)(b*32 + col0-31))*HWn + hwp;
                    o1[i0] = sigmoidf_(v0 + bias_s[col0])   * __ldg(hidden + i0);
                    o1[i1] = sigmoidf_(v1 + bias_s[col0+1]) * __ldg(hidden + i1);
                }
            }
        }
    } else if (MODE == 1){
        #pragma unroll
        for (int mt = 0; mt < 2; ++mt)
        #pragma unroll
        for (int half = 0; half < 2; ++half){
            int pl  = w*32 + mt*16 + r + 8*half;
            int hwp = hwb + pl;
            #pragma unroll
            for (int nt = 0; nt < NT; ++nt){
                int col0 = nt*8 + cq*2;
                float v0 = half ? acc[mt][nt].z : acc[mt][nt].x;
                float v1 = half ? acc[mt][nt].w : acc[mt][nt].y;
                float q0 = tanhf(v0 + bias_s[col0]);
                float q1 = tanhf(v1 + bias_s[col0+1]);
                size_t i0 = ((size_t)(b*32 + col0  ))*HWn + hwp;
                size_t i1 = ((size_t)(b*32 + col0+1))*HWn + hwp;
                float z0 = __ldg(zbuf + i0), z1 = __ldg(zbuf + i1);
                o0[i0] = (1.f - z0)*__ldg(hidden + i0) + z0*q0;
                o0[i1] = (1.f - z1)*__ldg(hidden + i1) + z1*q1;
            }
        }
    } else {
        float cb = __ldg(ch2b);
        __syncthreads();    // all warps done with A smem before overlay
        float ps[2][2] = {{0.f,0.f},{0.f,0.f}};
        #pragma unroll
        for (int mt = 0; mt < 2; ++mt)
        #pragma unroll
        for (int half = 0; half < 2; ++half){
            int pl = w*32 + mt*16 + r + 8*half;
            #pragma unroll
            for (int nt = 0; nt < NT; ++nt){
                int col0 = nt*8 + cq*2;
                float v0 = half ? acc[mt][nt].z : acc[mt][nt].x;
                float v1 = half ? acc[mt][nt].w : acc[mt][nt].y;
                v0 = fmaxf(v0, 0.f);
                v1 = fmaxf(v1, 0.f);
                if (nt < 4){                     // dh1 -> A1 smem
                    A1[pl*33 + col0  ] = v0;
                    A1[pl*33 + col0+1] = v1;
                } else {                         // ch1 -> conf partial
                    ps[mt][half] = fmaf(v0, bias_s[col0-32],
                                   fmaf(v1, bias_s[col0-31], ps[mt][half]));
                }
            }
        }
        #pragma unroll
        for (int mt = 0; mt < 2; ++mt)
        #pragma unroll
        for (int half = 0; half < 2; ++half){
            float p = ps[mt][half];
            p += __shfl_xor_sync(0xffffffffu, p, 1);
            p += __shfl_xor_sync(0xffffffffu, p, 2);
            if (cq == 0){
                int pl = w*32 + mt*16 + r + 8*half;
                int g  = gp0 + pl;
                float cs = cb + p;
                o2[g] = cs;
                o1[g] = sigmoidf_(cs);
            }
        }
        __syncthreads();
        float a[32];
        #pragma unroll
        for (int ic = 0; ic < 32; ++ic) a[ic] = A1[tid*33 + ic];
        float t2[64];
        #pragma unroll
        for (int i = 0; i < 64; ++i) t2[i] = 0.f;
        #pragma unroll
        for (int ic = 0; ic < 32; ++ic){
            float vv = a[ic];
            const float4* wr = (const float4*)(extra + ic*64);
            #pragma unroll
            for (int q4 = 0; q4 < 16; ++q4){
                float4 w4 = wr[q4];
                t2[q4*4+0] = fmaf(vv, w4.x, t2[q4*4+0]);
                t2[q4*4+1] = fmaf(vv, w4.y, t2[q4*4+1]);
                t2[q4*4+2] = fmaf(vv, w4.z, t2[q4*4+2]);
                t2[q4*4+3] = fmaf(vv, w4.w, t2[q4*4+3]);
            }
        }
        int g = gp0 + tid;
        #pragma unroll
        for (int oc = 0; oc < 64; ++oc)
            o0[(size_t)oc*NPIX + g] = fmaxf(t2[oc], 0.f);
    }
}

// ---------------- logits (64->256) + softmax + windowed depth regression -----
__global__ void __launch_bounds__(256) softmax_head(
                             const float* __restrict__ t2g,
                             const float* __restrict__ w3,
                             const float* __restrict__ b3,
                             float* __restrict__ prob,
                             float* __restrict__ nd)
{
    extern __shared__ float smem[];
    float* w3_s = smem;                   // 256*64
    float* t2_s = w3_s + 256*64;          // [32][65]
    float* b3_s = t2_s + 32*65;           // 256
    float* redA = b3_s + 256;             // [8][33]
    float* redB = redA + 8*33;
    int*   redI = (int*)(redB + 8*33);

    int tid = threadIdx.x;
    for (int i = tid; i < 256*64/4; i += blockDim.x)
        reinterpret_cast<float4*>(w3_s)[i] = reinterpret_cast<const float4*>(w3)[i];
    if (tid < 256) b3_s[tid] = b3[tid];

    int g0 = blockIdx.x * 32;
    #pragma unroll
    for (int i = 0; i < 8; i++) {
        int idx = tid + i*256;
        int k = idx >> 5; int l = idx & 31;
        t2_s[l*65 + k] = t2g[(size_t)k*NPIX + g0 + l];
    }
    __syncthreads();

    int w = tid >> 5;
    int l = tid & 31;
    int g = g0 + l;
    int b  = g / HWn;
    int hw = g - b*HWn;

    // hold the pixel's 64 t2 values in registers (w3 loads become broadcast)
    float t2v[64];
    {
        const float* t2r = t2_s + l*65;
        #pragma unroll
        for (int k = 0; k < 64; ++k) t2v[k] = t2r[k];
    }

    float lg[32];
    float lmax = -3.4e38f; int lamax = 0;
    #pragma unroll
    for (int j = 0; j < 32; j++) {
        int oc = w*32 + j;
        float acc = b3_s[oc];
        const float4* wrow = (const float4*)(w3_s + oc*64);
        #pragma unroll
        for (int k4 = 0; k4 < 16; k4++) {
            float4 wv = wrow[k4];
            acc = fmaf(t2v[k4*4+0], wv.x, acc);
            acc = fmaf(t2v[k4*4+1], wv.y, acc);
            acc = fmaf(t2v[k4*4+2], wv.z, acc);
            acc = fmaf(t2v[k4*4+3], wv.w, acc);
        }
        lg[j] = acc;
        if (acc > lmax) { lmax = acc; lamax = oc; }
    }

    redA[w*33 + l] = lmax; redI[w*33 + l] = lamax;
    __syncthreads();
    float M = -3.4e38f; int A = 0;
    #pragma unroll
    for (int ww = 0; ww < 8; ww++) {
        float m = redA[ww*33 + l];
        if (m > M) { M = m; A = redI[ww*33 + l]; }
    }

    float s = 0.f;
    #pragma unroll
    for (int j = 0; j < 32; j++) { lg[j] = __expf(lg[j] - M); s += lg[j]; }
    __syncthreads();
    redA[w*33 + l] = s;
    __syncthreads();
    float S = 0.f;
    #pragma unroll
    for (int ww = 0; ww < 8; ww++) S += redA[ww*33 + l];
    float rS = 1.f / S;

    int lo = A - 4, hi = A + 4;
    int ocl = lo < 0 ? 0 : lo;
    int och = hi > 255 ? 255 : hi;
    float num = 0.f, den = 0.f;
    #pragma unroll
    for (int j = 0; j < 32; j++) {
        int oc = w*32 + j;
        if (oc >= ocl && oc <= och) {
            float mult = 1.f;
            if (oc == 0   && lo < 0)   mult += (float)(-lo);
            if (oc == 255 && hi > 255) mult += (float)(hi - 255);
            float pv = lg[j] * rS;
            num = fmaf(mult * (float)oc, pv, num);
            den = fmaf(mult, pv, den);
        }
    }
    __syncthreads();
    redA[w*33 + l] = num; redB[w*33 + l] = den;
    __syncthreads();
    if (w == 0) {
        float Nv = 0.f, D = 0.f;
        #pragma unroll
        for (int ww = 0; ww < 8; ww++) { Nv += redA[ww*33 + l]; D += redB[ww*33 + l]; }
        nd[g] = (Nv / (1e-6f + D)) * (1.0f / 255.0f);
    }

    float* pbase = prob + (size_t)b*NSn*HWn + hw;
    #pragma unroll
    for (int j = 0; j < 32; j++)
        pbase[(size_t)(w*32 + j)*HWn] = lg[j] * rS;
}

// ---------------- launch ------------------------------------------------------
extern "C" void kernel_launch(void* const* d_in, const int* in_sizes, int n_in,
                              void* d_out, int out_size)
{
    const float* hidden  = (const float*)d_in[0];
    const float* ndep    = (const float*)d_in[1];
    const float* corr    = (const float*)d_in[2];
    const float* convz_w = (const float*)d_in[3];
    const float* convz_b = (const float*)d_in[4];
    const float* convr_w = (const float*)d_in[5];
    const float* convr_b = (const float*)d_in[6];
    const float* convq_w = (const float*)d_in[7];
    const float* convq_b = (const float*)d_in[8];
    const float* dh1_w   = (const float*)d_in[9];
    const float* dh2_w   = (const float*)d_in[10];
    const float* dh3_w   = (const float*)d_in[11];
    const float* dh3_b   = (const float*)d_in[12];
    const float* ch1_w   = (const float*)d_in[13];
    const float* ch2_w   = (const float*)d_in[14];
    const float* ch2_b   = (const float*)d_in[15];

    float* out = (float*)d_out;
    float* out_h     = out;
    float* out_nd    = out_h  + (size_t)NPIX*32;
    float* out_prob  = out_nd + NPIX;
    float* out_conf  = out_prob + (size_t)NPIX*256;
    float* out_conf0 = out_conf + NPIX;

    float* zbuf;  cudaGetSymbolAddress((void**)&zbuf,  g_z);
    float* rhbuf; cudaGetSymbolAddress((void**)&rhbuf, g_rh);
    float* t2buf; cudaGetSymbolAddress((void**)&t2buf, g_t2);

    const int SMEM_M0 = 32768 + 2*64*128 + 256;          // 49408
    const int SMEM_M1 = 32768 + 2*32*128 + 256;          // 41216
    const int SMEM_M2 = 32768 + 2*64*128 + 256 + 8192;   // 57600
    const int SMEM_SMAX = (256*64 + 32*65 + 256 + 3*8*33)*4;

    cudaFuncSetAttribute(conv_mma<0>, cudaFuncAttributeMaxDynamicSharedMemorySize, SMEM_M0);
    cudaFuncSetAttribute(conv_mma<1>, cudaFuncAttributeMaxDynamicSharedMemorySize, SMEM_M1);
    cudaFuncSetAttribute(conv_mma<2>, cudaFuncAttributeMaxDynamicSharedMemorySize, SMEM_M2);
    cudaFuncSetAttribute(softmax_head, cudaFuncAttributeMaxDynamicSharedMemorySize, SMEM_SMAX);

    dim3 blk(128);
    dim3 grd(NPIX / 128);   // 2560

    conv_mma<0><<<grd, blk, SMEM_M0>>>(hidden, ndep, corr, convz_w, convr_w,
                                       convz_b, convr_b, hidden, nullptr,
                                       nullptr, nullptr, nullptr,
                                       zbuf, rhbuf, nullptr);
    conv_mma<1><<<grd, blk, SMEM_M1>>>(rhbuf, ndep, corr, convq_w, nullptr,
                                       convq_b, nullptr, hidden, zbuf,
                                       nullptr, nullptr, nullptr,
                                       out_h, nullptr, nullptr);
    conv_mma<2><<<grd, blk, SMEM_M2>>>(out_h, nullptr, nullptr, dh1_w, ch1_w,
                                       nullptr, nullptr, nullptr, nullptr,
                                       dh2_w, ch2_w, ch2_b,
                                       t2buf, out_conf, out_conf0);
    softmax_head<<<NPIX / 32, 256, SMEM_SMAX>>>(t2buf, dh3_w, dh3_b,
                                                out_prob, out_nd);
}

// round 5
// speedup vs baseline: 1.0714x; 1.0111x over previous
#include <cuda_runtime.h>
#include <cuda_fp16.h>
#include <cstdint>
#include <math.h>

#define Bn 4
#define Hn 256
#define Wn 320
#define HWn (Hn*Wn)          // 81920
#define NPIX (Bn*HWn)        // 327680
#define NSn 256

// ---------------- scratch (device globals) -----------------------------------
__device__ float g_z [(size_t)NPIX*32];
__device__ float g_rh[(size_t)NPIX*32];
__device__ float g_t2[(size_t)64*NPIX];

// ---------------- helpers -----------------------------------------------------
__device__ __forceinline__ uint32_t smem_u32(const void* p){
    uint32_t a;
    asm("{ .reg .u64 t; cvta.to.shared.u64 t, %1; cvt.u32.u64 %0, t; }" : "=r"(a) : "l"(p));
    return a;
}
__device__ __forceinline__ void ldm_x4(uint32_t* r, uint32_t addr){
    asm volatile("ldmatrix.sync.aligned.m8n8.x4.shared.b16 {%0,%1,%2,%3}, [%4];"
        : "=r"(r[0]), "=r"(r[1]), "=r"(r[2]), "=r"(r[3]) : "r"(addr));
}
__device__ __forceinline__ void mma16(float4& d, const uint32_t* a, uint32_t b0, uint32_t b1){
    asm volatile("mma.sync.aligned.m16n8k16.row.col.f32.f16.f16.f32 "
        "{%0,%1,%2,%3},{%4,%5,%6,%7},{%8,%9},{%0,%1,%2,%3};"
        : "+f"(d.x), "+f"(d.y), "+f"(d.z), "+f"(d.w)
        : "r"(a[0]), "r"(a[1]), "r"(a[2]), "r"(a[3]), "r"(b0), "r"(b1));
}
__device__ __forceinline__ float sigmoidf_(float v){ return 1.f/(1.f+__expf(-v)); }
// SW128 swizzle, 16B granularity: row-major 8-row cores of 128B rows
__device__ __forceinline__ uint32_t swzb(int row, int c16){
    return ((uint32_t)(row >> 3) << 10) | ((uint32_t)(row & 7) << 7)
         | ((uint32_t)((c16 ^ (row & 7)) & 7) << 4);
}

// ---------------- implicit-GEMM conv via mma.sync fp16x3 + ldmatrix ----------
// MODE 0: zr  — in 65ch dil1, N=64 (z|r)   -> g_z, g_rh
// MODE 1: q   — in 65ch dil1, N=32         -> h
// MODE 2: hd  — in 32ch dil2, N=64 (dh1|ch1) + dh2 + conf -> g_t2, conf, conf0
template<int MODE>
__global__ void __launch_bounds__(128) conv_mma(
    const float* __restrict__ in0,
    const float* __restrict__ ndep,
    const float* __restrict__ corr,
    const float* __restrict__ wA,
    const float* __restrict__ wB,
    const float* __restrict__ biasA,
    const float* __restrict__ biasB,
    const float* __restrict__ hidden,
    const float* __restrict__ zbuf,
    const float* __restrict__ dh2w,
    const float* __restrict__ ch2w,
    const float* __restrict__ ch2b,
    float* __restrict__ o0,
    float* __restrict__ o1,
    float* __restrict__ o2)
{
    constexpr int N    = (MODE == 1) ? 32 : 64;
    constexpr int NT   = N / 8;
    constexpr int NTP  = N / 16;
    constexpr int NCH  = (MODE == 2) ? 32 : 65;
    constexpr int KTOT = NCH * 9;                       // 585 or 288
    constexpr int NCHK = (KTOT + 63) / 64;              // 10 or 5
    constexpr int DIL  = (MODE == 2) ? 2 : 1;

    extern __shared__ char sm[];
    char* Ah = sm;                       // 128 x 128B (swizzled) fp16 hi
    char* Al = sm + 16384;               // fp16 lo
    char* Bh = sm + 32768;               // N x 128B
    char* Bl = Bh + N*128;
    float* bias_s = (float*)(Bl + N*128);      // [64]
    float* extra  = bias_s + 64;               // MODE2: dh2w [ic][64]
    float* A1     = (float*)Ah;                // MODE2 overlay [128][33]

    uint32_t AhS = smem_u32(Ah);
    uint32_t AlS = smem_u32(Al);
    uint32_t BhS = smem_u32(Bh);
    uint32_t BlS = smem_u32(Bl);

    int tid  = threadIdx.x;
    int lane = tid & 31;
    int w    = tid >> 5;
    int r    = lane >> 2;
    int cq   = lane & 3;

    if (MODE == 0){
        if (tid < 32)      bias_s[tid] = biasA[tid];
        else if (tid < 64) bias_s[tid] = biasB[tid-32];
    } else if (MODE == 1){
        if (tid < 32) bias_s[tid] = biasA[tid];
    } else {
        for (int e = tid; e < 2048; e += 128){
            int ic = e >> 6, oc = e & 63;
            extra[e] = dh2w[oc*32 + ic];
        }
        if (tid < 32) bias_s[tid] = ch2w[tid];
    }

    int gp0 = blockIdx.x * 128;
    int b   = gp0 / HWn;
    int hwb = gp0 - b*HWn;
    int hw  = hwb + tid;
    int y   = hw / Wn;
    int x   = hw - y*Wn;

    auto gatherA = [&](int kk) -> float {
        if (kk >= KTOT) return 0.f;
        int ic = kk / 9; int j = kk - ic*9;
        int j3 = j / 3;
        int dy = j3 - 1, dx = j - j3*3 - 1;
        int yy = y + dy*DIL, xx = x + dx*DIL;
        if (yy < 0 || yy >= Hn || xx < 0 || xx >= Wn) return 0.f;
        const float* s;
        if (MODE == 2)     s = in0  + ((size_t)(b*32 + ic))*HWn;
        else if (ic < 32)  s = in0  + ((size_t)(b*32 + ic))*HWn;
        else if (ic == 32) s = ndep + (size_t)b*HWn;
        else               s = corr + ((size_t)(b*32 + ic - 33))*HWn;
        return __ldg(s + yy*Wn + xx);
    };

    float4 acc[2][NT];
    #pragma unroll
    for (int mt = 0; mt < 2; ++mt)
        #pragma unroll
        for (int nt = 0; nt < NT; ++nt)
            acc[mt][nt] = make_float4(0.f, 0.f, 0.f, 0.f);

    for (int c = 0; c < NCHK; ++c){
        __syncthreads();   // previous chunk fully consumed

        // ---- stage A: this thread's pixel row, 64 k values ----
        #pragma unroll
        for (int c16 = 0; c16 < 8; ++c16){
            uint32_t hu[4], lu[4];
            #pragma unroll
            for (int p = 0; p < 4; ++p){
                float v0 = gatherA(c*64 + c16*8 + p*2);
                float v1 = gatherA(c*64 + c16*8 + p*2 + 1);
                __half h0 = __float2half_rn(v0), h1 = __float2half_rn(v1);
                __half l0 = __float2half_rn(v0 - __half2float(h0));
                __half l1 = __float2half_rn(v1 - __half2float(h1));
                hu[p] = (uint32_t)__half_as_ushort(h0) | ((uint32_t)__half_as_ushort(h1) << 16);
                lu[p] = (uint32_t)__half_as_ushort(l0) | ((uint32_t)__half_as_ushort(l1) << 16);
            }
            uint32_t off = swzb(tid, c16);
            *(uint4*)(Ah + off) = make_uint4(hu[0], hu[1], hu[2], hu[3]);
            *(uint4*)(Al + off) = make_uint4(lu[0], lu[1], lu[2], lu[3]);
        }

        // ---- stage B: weight rows ----
        #pragma unroll
        for (int e = tid; e < N*8; e += 128){
            int n = e >> 3, c16 = e & 7;
            const float* ws = (MODE == 1) ? (wA + n*KTOT)
                            : (n < 32 ? wA + n*KTOT : wB + (n-32)*KTOT);
            uint32_t hu[4], lu[4];
            #pragma unroll
            for (int p = 0; p < 4; ++p){
                int k0 = c*64 + c16*8 + p*2;
                float v0 = (k0     < KTOT) ? __ldg(ws + k0)     : 0.f;
                float v1 = (k0 + 1 < KTOT) ? __ldg(ws + k0 + 1) : 0.f;
                __half h0 = __float2half_rn(v0), h1 = __float2half_rn(v1);
                __half l0 = __float2half_rn(v0 - __half2float(h0));
                __half l1 = __float2half_rn(v1 - __half2float(h1));
                hu[p] = (uint32_t)__half_as_ushort(h0) | ((uint32_t)__half_as_ushort(h1) << 16);
                lu[p] = (uint32_t)__half_as_ushort(l0) | ((uint32_t)__half_as_ushort(l1) << 16);
            }
            uint32_t off = swzb(n, c16);
            *(uint4*)(Bh + off) = make_uint4(hu[0], hu[1], hu[2], hu[3]);
            *(uint4*)(Bl + off) = make_uint4(lu[0], lu[1], lu[2], lu[3]);
        }

        __syncthreads();

        // ---- 4 k16 steps ----
        #pragma unroll
        for (int ks = 0; ks < 4; ++ks){
            uint32_t ah[2][4], al[2][4];
            #pragma unroll
            for (int mt = 0; mt < 2; ++mt){
                int rowA = w*32 + mt*16 + (lane & 15);
                uint32_t off = ((uint32_t)(rowA >> 3) << 10) | ((uint32_t)(rowA & 7) << 7)
                             | ((uint32_t)(((ks*2 + (lane >> 4)) ^ (rowA & 7)) & 7) << 4);
                ldm_x4(ah[mt], AhS + off);
                ldm_x4(al[mt], AlS + off);
            }
            #pragma unroll
            for (int ntp = 0; ntp < NTP; ++ntp){
                int rowB = ntp*16 + (lane & 7) + ((lane >> 4) << 3);
                uint32_t off = ((uint32_t)(rowB >> 3) << 10) | ((uint32_t)(rowB & 7) << 7)
                             | ((uint32_t)(((ks*2 + ((lane >> 3) & 1)) ^ (rowB & 7)) & 7) << 4);
                uint32_t bh[4], bl[4];
                ldm_x4(bh, BhS + off);
                ldm_x4(bl, BlS + off);
                #pragma unroll
                for (int mt = 0; mt < 2; ++mt){
                    mma16(acc[mt][ntp*2  ], ah[mt], bh[0], bh[1]);
                    mma16(acc[mt][ntp*2  ], ah[mt], bl[0], bl[1]);
                    mma16(acc[mt][ntp*2  ], al[mt], bh[0], bh[1]);
                    mma16(acc[mt][ntp*2+1], ah[mt], bh[2], bh[3]);
                    mma16(acc[mt][ntp*2+1], ah[mt], bl[2], bl[3]);
                    mma16(acc[mt][ntp*2+1], al[mt], bh[2], bh[3]);
                }
            }
        }
    }

    // ---------------- epilogues ----------------
    if (MODE == 0){
        #pragma unroll
        for (int mt = 0; mt < 2; ++mt)
        #pragma unroll
        for (int half = 0; half < 2; ++half){
            int pl  = w*32 + mt*16 + r + 8*half;
            int hwp = hwb + pl;
            #pragma unroll
            for (int nt = 0; nt < NT; ++nt){
                int col0 = nt*8 + cq*2;
                float v0 = half ? acc[mt][nt].z : acc[mt][nt].x;
                float v1 = half ? acc[mt][nt].w : acc[mt][nt].y;
                if (nt < 4){
                    o0[((size_t)(b*32 + col0  ))*HWn + hwp] = sigmoidf_(v0 + bias_s[col0]);
                    o0[((size_t)(b*32 + col0+1))*HWn + hwp] = sigmoidf_(v1 + bias_s[col0+1]);
                } else {
                    size_t i0 = ((size_t)(b*32 + col0-32))*HWn + hwp;
                    size_t i1 = ((size_t)(b*32 + col0-31))*HWn + hwp;
                    o1[i0] = sigmoidf_(v0 + bias_s[col0])   * __ldg(hidden + i0);
                    o1[i1] = sigmoidf_(v1 + bias_s[col0+1]) * __ldg(hidden + i1);
                }
            }
        }
    } else if (MODE == 1){
        #pragma unroll
        for (int mt = 0; mt < 2; ++mt)
        #pragma unroll
        for (int half = 0; half < 2; ++half){
            int pl  = w*32 + mt*16 + r + 8*half;
            int hwp = hwb + pl;
            #pragma unroll
            for (int nt = 0; nt < NT; ++nt){
                int col0 = nt*8 + cq*2;
                float v0 = half ? acc[mt][nt].z : acc[mt][nt].x;
                float v1 = half ? acc[mt][nt].w : acc[mt][nt].y;
                float q0 = tanhf(v0 + bias_s[col0]);
                float q1 = tanhf(v1 + bias_s[col0+1]);
                size_t i0 = ((size_t)(b*32 + col0  ))*HWn + hwp;
                size_t i1 = ((size_t)(b*32 + col0+1))*HWn + hwp;
                float z0 = __ldg(zbuf + i0), z1 = __ldg(zbuf + i1);
                o0[i0] = (1.f - z0)*__ldg(hidden + i0) + z0*q0;
                o0[i1] = (1.f - z1)*__ldg(hidden + i1) + z1*q1;
            }
        }
    } else {
        float cb = __ldg(ch2b);
        __syncthreads();    // all warps done with A smem before overlay
        float ps[2][2] = {{0.f,0.f},{0.f,0.f}};
        #pragma unroll
        for (int mt = 0; mt < 2; ++mt)
        #pragma unroll
        for (int half = 0; half < 2; ++half){
            int pl = w*32 + mt*16 + r + 8*half;
            #pragma unroll
            for (int nt = 0; nt < NT; ++nt){
                int col0 = nt*8 + cq*2;
                float v0 = half ? acc[mt][nt].z : acc[mt][nt].x;
                float v1 = half ? acc[mt][nt].w : acc[mt][nt].y;
                v0 = fmaxf(v0, 0.f);
                v1 = fmaxf(v1, 0.f);
                if (nt < 4){                     // dh1 -> A1 smem
                    A1[pl*33 + col0  ] = v0;
                    A1[pl*33 + col0+1] = v1;
                } else {                         // ch1 -> conf partial
                    ps[mt][half] = fmaf(v0, bias_s[col0-32],
                                   fmaf(v1, bias_s[col0-31], ps[mt][half]));
                }
            }
        }
        #pragma unroll
        for (int mt = 0; mt < 2; ++mt)
        #pragma unroll
        for (int half = 0; half < 2; ++half){
            float p = ps[mt][half];
            p += __shfl_xor_sync(0xffffffffu, p, 1);
            p += __shfl_xor_sync(0xffffffffu, p, 2);
            if (cq == 0){
                int pl = w*32 + mt*16 + r + 8*half;
                int g  = gp0 + pl;
                float cs = cb + p;
                o2[g] = cs;
                o1[g] = sigmoidf_(cs);
            }
        }
        __syncthreads();
        float a[32];
        #pragma unroll
        for (int ic = 0; ic < 32; ++ic) a[ic] = A1[tid*33 + ic];
        float t2[64];
        #pragma unroll
        for (int i = 0; i < 64; ++i) t2[i] = 0.f;
        #pragma unroll
        for (int ic = 0; ic < 32; ++ic){
            float vv = a[ic];
            const float4* wr = (const float4*)(extra + ic*64);
            #pragma unroll
            for (int q4 = 0; q4 < 16; ++q4){
                float4 w4 = wr[q4];
                t2[q4*4+0] = fmaf(vv, w4.x, t2[q4*4+0]);
                t2[q4*4+1] = fmaf(vv, w4.y, t2[q4*4+1]);
                t2[q4*4+2] = fmaf(vv, w4.z, t2[q4*4+2]);
                t2[q4*4+3] = fmaf(vv, w4.w, t2[q4*4+3]);
            }
        }
        int g = gp0 + tid;
        #pragma unroll
        for (int oc = 0; oc < 64; ++oc)
            o0[(size_t)oc*NPIX + g] = fmaxf(t2[oc], 0.f);
    }
}

// ---------------- logits (64->256) + softmax + windowed depth regression -----
__global__ void __launch_bounds__(256) softmax_head(
                             const float* __restrict__ t2g,
                             const float* __restrict__ w3,
                             const float* __restrict__ b3,
                             float* __restrict__ prob,
                             float* __restrict__ nd)
{
    extern __shared__ float smem[];
    float* w3_s = smem;                   // 256*64
    float* t2_s = w3_s + 256*64;          // [32][65]
    float* b3_s = t2_s + 32*65;           // 256
    float* redA = b3_s + 256;             // [8][33]
    float* redB = redA + 8*33;
    int*   redI = (int*)(redB + 8*33);

    int tid = threadIdx.x;
    for (int i = tid; i < 256*64/4; i += blockDim.x)
        reinterpret_cast<float4*>(w3_s)[i] = reinterpret_cast<const float4*>(w3)[i];
    if (tid < 256) b3_s[tid] = b3[tid];

    int g0 = blockIdx.x * 32;
    #pragma unroll
    for (int i = 0; i < 8; i++) {
        int idx = tid + i*256;
        int k = idx >> 5; int l = idx & 31;
        t2_s[l*65 + k] = t2g[(size_t)k*NPIX + g0 + l];
    }
    __syncthreads();

    int w = tid >> 5;
    int l = tid & 31;
    int g = g0 + l;
    int b  = g / HWn;
    int hw = g - b*HWn;

    // hold the pixel's 64 t2 values in registers (w3 loads become broadcast)
    float t2v[64];
    {
        const float* t2r = t2_s + l*65;
        #pragma unroll
        for (int k = 0; k < 64; ++k) t2v[k] = t2r[k];
    }

    float lg[32];
    float lmax = -3.4e38f; int lamax = 0;
    #pragma unroll
    for (int j = 0; j < 32; j++) {
        int oc = w*32 + j;
        float acc = b3_s[oc];
        const float4* wrow = (const float4*)(w3_s + oc*64);
        #pragma unroll
        for (int k4 = 0; k4 < 16; k4++) {
            float4 wv = wrow[k4];
            acc = fmaf(t2v[k4*4+0], wv.x, acc);
            acc = fmaf(t2v[k4*4+1], wv.y, acc);
            acc = fmaf(t2v[k4*4+2], wv.z, acc);
            acc = fmaf(t2v[k4*4+3], wv.w, acc);
        }
        lg[j] = acc;
        if (acc > lmax) { lmax = acc; lamax = oc; }
    }

    redA[w*33 + l] = lmax; redI[w*33 + l] = lamax;
    __syncthreads();
    float M = -3.4e38f; int A = 0;
    #pragma unroll
    for (int ww = 0; ww < 8; ww++) {
        float m = redA[ww*33 + l];
        if (m > M) { M = m; A = redI[ww*33 + l]; }
    }

    float s = 0.f;
    #pragma unroll
    for (int j = 0; j < 32; j++) { lg[j] = __expf(lg[j] - M); s += lg[j]; }
    __syncthreads();
    redA[w*33 + l] = s;
    __syncthreads();
    float S = 0.f;
    #pragma unroll
    for (int ww = 0; ww < 8; ww++) S += redA[ww*33 + l];
    float rS = 1.f / S;

    int lo = A - 4, hi = A + 4;
    int ocl = lo < 0 ? 0 : lo;
    int och = hi > 255 ? 255 : hi;
    float num = 0.f, den = 0.f;
    #pragma unroll
    for (int j = 0; j < 32; j++) {
        int oc = w*32 + j;
        if (oc >= ocl && oc <= och) {
            float mult = 1.f;
            if (oc == 0   && lo < 0)   mult += (float)(-lo);
            if (oc == 255 && hi > 255) mult += (float)(hi - 255);
            float pv = lg[j] * rS;
            num = fmaf(mult * (float)oc, pv, num);
            den = fmaf(mult, pv, den);
        }
    }
    __syncthreads();
    redA[w*33 + l] = num; redB[w*33 + l] = den;
    __syncthreads();
    if (w == 0) {
        float Nv = 0.f, D = 0.f;
        #pragma unroll
        for (int ww = 0; ww < 8; ww++) { Nv += redA[ww*33 + l]; D += redB[ww*33 + l]; }
        nd[g] = (Nv / (1e-6f + D)) * (1.0f / 255.0f);
    }

    float* pbase = prob + (size_t)b*NSn*HWn + hw;
    #pragma unroll
    for (int j = 0; j < 32; j++)
        pbase[(size_t)(w*32 + j)*HWn] = lg[j] * rS;
}

// ---------------- launch ------------------------------------------------------
extern "C" void kernel_launch(void* const* d_in, const int* in_sizes, int n_in,
                              void* d_out, int out_size)
{
    const float* hidden  = (const float*)d_in[0];
    const float* ndep    = (const float*)d_in[1];
    const float* corr    = (const float*)d_in[2];
    const float* convz_w = (const float*)d_in[3];
    const float* convz_b = (const float*)d_in[4];
    const float* convr_w = (const float*)d_in[5];
    const float* convr_b = (const float*)d_in[6];
    const float* convq_w = (const float*)d_in[7];
    const float* convq_b = (const float*)d_in[8];
    const float* dh1_w   = (const float*)d_in[9];
    const float* dh2_w   = (const float*)d_in[10];
    const float* dh3_w   = (const float*)d_in[11];
    const float* dh3_b   = (const float*)d_in[12];
    const float* ch1_w   = (const float*)d_in[13];
    const float* ch2_w   = (const float*)d_in[14];
    const float* ch2_b   = (const float*)d_in[15];

    float* out = (float*)d_out;
    float* out_h     = out;
    float* out_nd    = out_h  + (size_t)NPIX*32;
    float* out_prob  = out_nd + NPIX;
    float* out_conf  = out_prob + (size_t)NPIX*256;
    float* out_conf0 = out_conf + NPIX;

    float* zbuf;  cudaGetSymbolAddress((void**)&zbuf,  g_z);
    float* rhbuf; cudaGetSymbolAddress((void**)&rhbuf, g_rh);
    float* t2buf; cudaGetSymbolAddress((void**)&t2buf, g_t2);

    const int SMEM_M0 = 32768 + 2*64*128 + 256;          // 49408
    const int SMEM_M1 = 32768 + 2*32*128 + 256;          // 41216
    const int SMEM_M2 = 32768 + 2*64*128 + 256 + 8192;   // 57600
    const int SMEM_SMAX = (256*64 + 32*65 + 256 + 3*8*33)*4;

    cudaFuncSetAttribute(conv_mma<0>, cudaFuncAttributeMaxDynamicSharedMemorySize, SMEM_M0);
    cudaFuncSetAttribute(conv_mma<1>, cudaFuncAttributeMaxDynamicSharedMemorySize, SMEM_M1);
    cudaFuncSetAttribute(conv_mma<2>, cudaFuncAttributeMaxDynamicSharedMemorySize, SMEM_M2);
    cudaFuncSetAttribute(softmax_head, cudaFuncAttributeMaxDynamicSharedMemorySize, SMEM_SMAX);

    dim3 blk(128);
    dim3 grd(NPIX / 128);   // 2560

    conv_mma<0><<<grd, blk, SMEM_M0>>>(hidden, ndep, corr, convz_w, convr_w,
                                       convz_b, convr_b, hidden, nullptr,
                                       nullptr, nullptr, nullptr,
                                       zbuf, rhbuf, nullptr);
    conv_mma<1><<<grd, blk, SMEM_M1>>>(rhbuf, ndep, corr, convq_w, nullptr,
                                       convq_b, nullptr, hidden, zbuf,
                                       nullptr, nullptr, nullptr,
                                       out_h, nullptr, nullptr);
    conv_mma<2><<<grd, blk, SMEM_M2>>>(out_h, nullptr, nullptr, dh1_w, ch1_w,
                                       nullptr, nullptr, nullptr, nullptr,
                                       dh2_w, ch2_w, ch2_b,
                                       t2buf, out_conf, out_conf0);
    softmax_head<<<NPIX / 32, 256, SMEM_SMAX>>>(t2buf, dh3_w, dh3_b,
                                                out_prob, out_nd);
}

// round 6
// speedup vs baseline: 1.9280x; 1.7995x over previous
#include <cuda_runtime.h>
#include <cuda_fp16.h>
#include <cstdint>
#include <math.h>

#define Bn 4
#define Hn 256
#define Wn 320
#define HWn (Hn*Wn)          // 81920
#define NPIX (Bn*HWn)        // 327680
#define NSn 256

// ---------------- device-global scratch --------------------------------------
__device__ __align__(16) char  g_p0[(size_t)NPIX*320];   // [pix][80ch hi|80ch lo] fp16 (hidden,ndep,corr)
__device__ __align__(16) char  g_p1[(size_t)NPIX*320];   // same, ch0-31 = rh (filled by MODE0)
__device__ __align__(16) char  g_p2[(size_t)NPIX*128];   // [pix][32ch hi|32ch lo] fp16 (h)
__device__ __align__(16) __half g_wb[175104];            // pre-converted weights, chunk-blocked
__device__ float g_z [(size_t)NPIX*32];
__device__ float g_t2[(size_t)64*NPIX];

// ---------------- helpers -----------------------------------------------------
__device__ __forceinline__ uint32_t smem_u32(const void* p){
    uint32_t a;
    asm("{ .reg .u64 t; cvta.to.shared.u64 t, %1; cvt.u32.u64 %0, t; }" : "=r"(a) : "l"(p));
    return a;
}
__device__ __forceinline__ void ldm_x4(uint32_t* r, uint32_t addr){
    asm volatile("ldmatrix.sync.aligned.m8n8.x4.shared.b16 {%0,%1,%2,%3}, [%4];"
        : "=r"(r[0]), "=r"(r[1]), "=r"(r[2]), "=r"(r[3]) : "r"(addr));
}
__device__ __forceinline__ void mma16(float4& d, const uint32_t* a, uint32_t b0, uint32_t b1){
    asm volatile("mma.sync.aligned.m16n8k16.row.col.f32.f16.f16.f32 "
        "{%0,%1,%2,%3},{%4,%5,%6,%7},{%8,%9},{%0,%1,%2,%3};"
        : "+f"(d.x), "+f"(d.y), "+f"(d.z), "+f"(d.w)
        : "r"(a[0]), "r"(a[1]), "r"(a[2]), "r"(a[3]), "r"(b0), "r"(b1));
}
__device__ __forceinline__ float sigmoidf_(float v){ return 1.f/(1.f+__expf(-v)); }

// ---------------- pre-kernel 1: input planes ----------------------------------
__global__ void __launch_bounds__(128) prep_inputs(
    const float* __restrict__ hidden,
    const float* __restrict__ ndep,
    const float* __restrict__ corr)
{
    __shared__ __half sm[128*160];       // [pix][80 hi | 80 lo]
    int tid = threadIdx.x;
    int g0 = blockIdx.x*128;
    int b = g0 / HWn, hwb = g0 - b*HWn;
    int hw = hwb + tid;

    #pragma unroll 1
    for (int ch = 0; ch < 80; ++ch){
        float v = 0.f;
        if (ch < 32)       v = hidden[(size_t)(b*32+ch)*HWn + hw];
        else if (ch == 32) v = ndep[(size_t)b*HWn + hw];
        else if (ch < 65)  v = corr[(size_t)(b*32+ch-33)*HWn + hw];
        __half h = __float2half_rn(v);
        sm[tid*160 + ch]      = h;
        sm[tid*160 + 80 + ch] = __float2half_rn(v - __half2float(h));
    }
    __syncthreads();

    // planes0: straight copy (layout identical)
    uint4* dst0 = (uint4*)(g_p0 + (size_t)g0*320);
    const uint4* src = (const uint4*)sm;
    #pragma unroll
    for (int i = 0; i < 20; ++i) dst0[tid + i*128] = src[tid + i*128];

    // planes1: static part = halves [32,80) hi and [112,160) lo per pixel
    for (int e = tid; e < 128*12; e += 128){
        int p = e / 12, u = e - p*12;
        int hb = (u < 6) ? (32 + u*8) : (112 + (u-6)*8);
        *(uint4*)(g_p1 + (size_t)(g0+p)*320 + hb*2) = *(const uint4*)(sm + p*160 + hb);
    }
}

// ---------------- pre-kernel 2: weight chunks ---------------------------------
// MODE0 (zr): 45 chunks x [64n x 16ch] hi then lo (2048 halves/chunk) at offset 0
// MODE1 (q):  45 chunks x [32n x 16ch] (1024 halves/chunk) at 92160
// MODE2 (hd): 18 chunks x [64n x 16ch] (2048 halves/chunk) at 138240
__global__ void prep_weights(
    const float* __restrict__ zw, const float* __restrict__ rw,
    const float* __restrict__ qw,
    const float* __restrict__ d1w, const float* __restrict__ c1w)
{
    int idx = blockIdx.x*256 + threadIdx.x;
    float v = 0.f;
    __half* dh;
    int loStep;
    if (idx < 46080){
        int kc = idx >> 10, rem = idx & 1023, n = rem >> 4, ci = rem & 15;
        int t = kc/5, ch = (kc - t*5)*16 + ci;
        if (ch < 65) v = (n < 32) ? zw[n*585 + ch*9 + t] : rw[(n-32)*585 + ch*9 + t];
        dh = g_wb + kc*2048 + n*16 + ci; loStep = 1024;
    } else if (idx < 69120){
        int j = idx - 46080;
        int kc = j >> 9, rem = j & 511, n = rem >> 4, ci = rem & 15;
        int t = kc/5, ch = (kc - t*5)*16 + ci;
        if (ch < 65) v = qw[n*585 + ch*9 + t];
        dh = g_wb + 92160 + kc*1024 + n*16 + ci; loStep = 512;
    } else if (idx < 87552){
        int j = idx - 69120;
        int kc = j >> 10, rem = j & 1023, n = rem >> 4, ci = rem & 15;
        int t = kc >> 1, ch = (kc & 1)*16 + ci;
        v = (n < 32) ? d1w[n*288 + ch*9 + t] : c1w[(n-32)*288 + ch*9 + t];
        dh = g_wb + 138240 + kc*2048 + n*16 + ci; loStep = 1024;
    } else return;
    __half h = __float2half_rn(v);
    dh[0]      = h;
    dh[loStep] = __float2half_rn(v - __half2float(h));
}

// ---------------- strip-resident shift-GEMM conv -------------------------------
// MODE 0: zr  (65ch pad80, dil1, N=64: z|r) -> g_z fp32, rh -> g_p1 planes
// MODE 1: q   (65ch pad80, dil1, N=32)      -> h fp32 (o0) + g_p2 planes
// MODE 2: hd  (32ch, dil2, N=64: dh1|ch1) + dh2 + conf -> g_t2, conf(o1), conf0(o2)
template<int MODE>
__global__ void __launch_bounds__(128) conv_mma(
    const float* __restrict__ biasA,
    const float* __restrict__ biasB,
    const float* __restrict__ hidden,
    const float* __restrict__ dh2w,
    const float* __restrict__ ch2w,
    const float* __restrict__ ch2b,
    float* __restrict__ o0,
    float* __restrict__ o1,
    float* __restrict__ o2)
{
    constexpr int N      = (MODE == 1) ? 32 : 64;
    constexpr int NCHK   = (MODE == 2) ? 18 : 45;
    constexpr int DIL    = (MODE == 2) ? 2 : 1;
    constexpr int SW     = 16 + 2*DIL;          // 18 / 20
    constexpr int SH     = 8 + 2*DIL;           // 10 / 12
    constexpr int PLANEB = (MODE == 2) ? 128 : 320;
    constexpr int ROWB   = (MODE == 2) ? 144 : 336;
    constexpr int LO_OFF = (MODE == 2) ? 64 : 160;
    constexpr int STRIPB = SH*SW*ROWB;
    constexpr int SLOTB  = N*96;                // hi N*48 + lo N*48
    constexpr int WOFF   = (MODE == 0) ? 0 : (MODE == 1) ? 92160 : 138240;
    constexpr int CHS    = N*32;                // halves per chunk block

    extern __shared__ char sm[];
    char*  strip = sm;
    char*  bbuf  = sm + STRIPB;
    float* dh2s  = (float*)(sm + STRIPB + 2*SLOTB);   // MODE2 only
    float* A1    = (float*)sm;                        // epilogue overlay

    int tid = threadIdx.x, lane = tid & 31, w = tid >> 5;
    int r = lane >> 2, cq = lane & 3;
    int bx0 = blockIdx.x*16, by0 = blockIdx.y*8, b = blockIdx.z;

    const char* plane = (MODE == 0) ? g_p0 : (MODE == 1) ? g_p1 : g_p2;

    // ---- strip load (once) ----
    constexpr int PU = PLANEB/16;
    constexpr int UT = SH*SW*PU;
    for (int e = tid; e < UT; e += 128){
        int sp = e/PU, u = e - sp*PU;
        int sy = sp/SW, sx = sp - sy*SW;
        int y = by0 - DIL + sy, x = bx0 - DIL + sx;
        uint4 v = make_uint4(0u,0u,0u,0u);
        if (y >= 0 && y < Hn && x >= 0 && x < Wn)
            v = __ldg((const uint4*)(plane + ((size_t)(b*HWn + y*Wn + x))*PLANEB) + u);
        *(uint4*)(strip + sp*ROWB + u*16) = v;
    }

    // ---- B chunk staging helper ----
    auto stageB = [&](int kc, int s){
        const __half* blk = g_wb + WOFF + (size_t)kc*CHS;
        char* dst = bbuf + s*SLOTB;
        #pragma unroll
        for (int e = tid; e < N*4; e += 128){
            int pl_ = e / (2*N);
            int f = e - pl_*2*N;
            int n = f >> 1, part = f & 1;
            uint4 v = *(const uint4*)(blk + e*8);
            *(uint4*)(dst + pl_*N*48 + n*48 + part*16) = v;
        }
    };
    stageB(0, 0);
    stageB(1, 1);

    if (MODE == 2){
        for (int e = tid; e < 2048; e += 128){
            int ic = e >> 6, oc = e & 63;
            dh2s[e] = dh2w[oc*32 + ic];
        }
    }
    __syncthreads();

    // ---- per-thread A fragment pixel bases ----
    uint32_t stripS = smem_u32(strip);
    uint32_t apix[2];
    #pragma unroll
    for (int mt = 0; mt < 2; ++mt){
        int p = w*32 + mt*16 + (lane & 15);
        apix[mt] = stripS + (uint32_t)(((p>>4)*SW + (p&15))*ROWB) + ((uint32_t)(lane>>4) << 4);
    }
    uint32_t bS = smem_u32(bbuf);

    float4 acc[2][N/8];
    #pragma unroll
    for (int mt = 0; mt < 2; ++mt)
        #pragma unroll
        for (int nt = 0; nt < N/8; ++nt)
            acc[mt][nt] = make_float4(0.f,0.f,0.f,0.f);

    // ---- K loop: chunk = (tap, 16 channels) ----
    for (int kc = 0; kc < NCHK; ++kc){
        int t, cc;
        if (MODE == 2){ t = kc >> 1; cc = kc & 1; }
        else          { t = kc/5;   cc = kc - t*5; }
        int j3 = t/3, jx = t - j3*3;
        uint32_t tap = (uint32_t)((j3*SW + jx)*DIL*ROWB) + (uint32_t)cc*32;
        uint32_t slot = bS + (uint32_t)(kc & 1)*SLOTB;

        uint32_t ah[2][4], al[2][4];
        #pragma unroll
        for (int mt = 0; mt < 2; ++mt){
            ldm_x4(ah[mt], apix[mt] + tap);
            ldm_x4(al[mt], apix[mt] + tap + LO_OFF);
        }
        #pragma unroll
        for (int ntp = 0; ntp < N/16; ++ntp){
            int rowB = ntp*16 + (lane & 7) + ((lane >> 4) << 3);
            uint32_t boff = slot + (uint32_t)(rowB*48 + ((lane >> 3) & 1)*16);
            uint32_t bh[4], bl[4];
            ldm_x4(bh, boff);
            ldm_x4(bl, boff + (uint32_t)N*48);
            #pragma unroll
            for (int mt = 0; mt < 2; ++mt){
                mma16(acc[mt][ntp*2  ], ah[mt], bh[0], bh[1]);
                mma16(acc[mt][ntp*2  ], ah[mt], bl[0], bl[1]);
                mma16(acc[mt][ntp*2  ], al[mt], bh[0], bh[1]);
                mma16(acc[mt][ntp*2+1], ah[mt], bh[2], bh[3]);
                mma16(acc[mt][ntp*2+1], ah[mt], bl[2], bl[3]);
                mma16(acc[mt][ntp*2+1], al[mt], bh[2], bh[3]);
            }
        }
        __syncthreads();
        if (kc + 2 < NCHK) stageB(kc + 2, kc & 1);
    }

    // ---------------- epilogues ----------------
    if (MODE == 0){
        // z -> g_z (o0), rh -> A1 smem then g_p1 planes
        #pragma unroll
        for (int mt = 0; mt < 2; ++mt)
        #pragma unroll
        for (int half = 0; half < 2; ++half){
            int p = w*32 + mt*16 + r + 8*half;
            int hwp = (by0 + (p>>4))*Wn + bx0 + (p&15);
            #pragma unroll
            for (int nt = 0; nt < 8; ++nt){
                int col = nt*8 + cq*2;
                float v0 = half ? acc[mt][nt].z : acc[mt][nt].x;
                float v1 = half ? acc[mt][nt].w : acc[mt][nt].y;
                if (nt < 4){
                    o0[((size_t)(b*32 + col  ))*HWn + hwp] = sigmoidf_(v0 + __ldg(biasA + col));
                    o0[((size_t)(b*32 + col+1))*HWn + hwp] = sigmoidf_(v1 + __ldg(biasA + col+1));
                } else {
                    int oc = col - 32;
                    size_t i0 = ((size_t)(b*32 + oc  ))*HWn + hwp;
                    size_t i1 = ((size_t)(b*32 + oc+1))*HWn + hwp;
                    A1[p*33 + oc  ] = sigmoidf_(v0 + __ldg(biasB + oc  )) * __ldg(hidden + i0);
                    A1[p*33 + oc+1] = sigmoidf_(v1 + __ldg(biasB + oc+1)) * __ldg(hidden + i1);
                }
            }
        }
        __syncthreads();
        {
            int p = tid;
            size_t g = (size_t)b*HWn + (by0 + (p>>4))*Wn + bx0 + (p&15);
            char* dst = g_p1 + g*320;
            #pragma unroll
            for (int u = 0; u < 4; ++u){
                __half hs[8], ls[8];
                #pragma unroll
                for (int i = 0; i < 8; ++i){
                    float v = A1[p*33 + u*8 + i];
                    __half h = __float2half_rn(v);
                    hs[i] = h;
                    ls[i] = __float2half_rn(v - __half2float(h));
                }
                *(uint4*)(dst + u*16)       = *(uint4*)hs;
                *(uint4*)(dst + 160 + u*16) = *(uint4*)ls;
            }
        }
    } else if (MODE == 1){
        // h -> o0 fp32 + A1 smem -> g_p2 planes
        #pragma unroll
        for (int mt = 0; mt < 2; ++mt)
        #pragma unroll
        for (int half = 0; half < 2; ++half){
            int p = w*32 + mt*16 + r + 8*half;
            int hwp = (by0 + (p>>4))*Wn + bx0 + (p&15);
            #pragma unroll
            for (int nt = 0; nt < 4; ++nt){
                int col = nt*8 + cq*2;
                float v0 = half ? acc[mt][nt].z : acc[mt][nt].x;
                float v1 = half ? acc[mt][nt].w : acc[mt][nt].y;
                float q0 = tanhf(v0 + __ldg(biasA + col));
                float q1 = tanhf(v1 + __ldg(biasA + col+1));
                size_t i0 = ((size_t)(b*32 + col  ))*HWn + hwp;
                size_t i1 = ((size_t)(b*32 + col+1))*HWn + hwp;
                float z0 = g_z[i0], z1 = g_z[i1];
                float h0 = (1.f - z0)*__ldg(hidden + i0) + z0*q0;
                float h1 = (1.f - z1)*__ldg(hidden + i1) + z1*q1;
                o0[i0] = h0;
                o0[i1] = h1;
                A1[p*33 + col  ] = h0;
                A1[p*33 + col+1] = h1;
            }
        }
        __syncthreads();
        {
            int p = tid;
            size_t g = (size_t)b*HWn + (by0 + (p>>4))*Wn + bx0 + (p&15);
            char* dst = g_p2 + g*128;
            #pragma unroll
            for (int u = 0; u < 4; ++u){
                __half hs[8], ls[8];
                #pragma unroll
                for (int i = 0; i < 8; ++i){
                    float v = A1[p*33 + u*8 + i];
                    __half h = __float2half_rn(v);
                    hs[i] = h;
                    ls[i] = __float2half_rn(v - __half2float(h));
                }
                *(uint4*)(dst + u*16)      = *(uint4*)hs;
                *(uint4*)(dst + 64 + u*16) = *(uint4*)ls;
            }
        }
    } else {
        float cb = __ldg(ch2b);
        float ps[2][2] = {{0.f,0.f},{0.f,0.f}};
        #pragma unroll
        for (int mt = 0; mt < 2; ++mt)
        #pragma unroll
        for (int half = 0; half < 2; ++half){
            int p = w*32 + mt*16 + r + 8*half;
            #pragma unroll
            for (int nt = 0; nt < 8; ++nt){
                int col = nt*8 + cq*2;
                float v0 = half ? acc[mt][nt].z : acc[mt][nt].x;
                float v1 = half ? acc[mt][nt].w : acc[mt][nt].y;
                v0 = fmaxf(v0, 0.f);
                v1 = fmaxf(v1, 0.f);
                if (nt < 4){
                    A1[p*33 + col  ] = v0;
                    A1[p*33 + col+1] = v1;
                } else {
                    ps[mt][half] = fmaf(v0, __ldg(ch2w + col-32),
                                   fmaf(v1, __ldg(ch2w + col-31), ps[mt][half]));
                }
            }
        }
        #pragma unroll
        for (int mt = 0; mt < 2; ++mt)
        #pragma unroll
        for (int half = 0; half < 2; ++half){
            float pp = ps[mt][half];
            pp += __shfl_xor_sync(0xffffffffu, pp, 1);
            pp += __shfl_xor_sync(0xffffffffu, pp, 2);
            if (cq == 0){
                int p = w*32 + mt*16 + r + 8*half;
                size_t g = (size_t)b*HWn + (by0 + (p>>4))*Wn + bx0 + (p&15);
                float cs = cb + pp;
                o2[g] = cs;
                o1[g] = sigmoidf_(cs);
            }
        }
        __syncthreads();
        float a[32];
        #pragma unroll
        for (int ic = 0; ic < 32; ++ic) a[ic] = A1[tid*33 + ic];
        float t2[64];
        #pragma unroll
        for (int i = 0; i < 64; ++i) t2[i] = 0.f;
        #pragma unroll
        for (int ic = 0; ic < 32; ++ic){
            float vv = a[ic];
            const float4* wr = (const float4*)(dh2s + ic*64);
            #pragma unroll
            for (int q4 = 0; q4 < 16; ++q4){
                float4 w4 = wr[q4];
                t2[q4*4+0] = fmaf(vv, w4.x, t2[q4*4+0]);
                t2[q4*4+1] = fmaf(vv, w4.y, t2[q4*4+1]);
                t2[q4*4+2] = fmaf(vv, w4.z, t2[q4*4+2]);
                t2[q4*4+3] = fmaf(vv, w4.w, t2[q4*4+3]);
            }
        }
        size_t g = (size_t)b*HWn + (by0 + (tid>>4))*Wn + bx0 + (tid&15);
        #pragma unroll
        for (int oc = 0; oc < 64; ++oc)
            o0[(size_t)oc*NPIX + g] = fmaxf(t2[oc], 0.f);
    }
}

// ---------------- logits (64->256) + softmax + windowed depth regression -----
__global__ void __launch_bounds__(256) softmax_head(
                             const float* __restrict__ t2g,
                             const float* __restrict__ w3,
                             const float* __restrict__ b3,
                             float* __restrict__ prob,
                             float* __restrict__ nd)
{
    extern __shared__ float smem[];
    float* w3_s = smem;                   // 256*64
    float* t2_s = w3_s + 256*64;          // [32][65]
    float* b3_s = t2_s + 32*65;           // 256
    float* redA = b3_s + 256;             // [8][33]
    float* redB = redA + 8*33;
    int*   redI = (int*)(redB + 8*33);

    int tid = threadIdx.x;
    for (int i = tid; i < 256*64/4; i += blockDim.x)
        reinterpret_cast<float4*>(w3_s)[i] = reinterpret_cast<const float4*>(w3)[i];
    if (tid < 256) b3_s[tid] = b3[tid];

    int g0 = blockIdx.x * 32;
    #pragma unroll
    for (int i = 0; i < 8; i++) {
        int idx = tid + i*256;
        int k = idx >> 5; int l = idx & 31;
        t2_s[l*65 + k] = t2g[(size_t)k*NPIX + g0 + l];
    }
    __syncthreads();

    int w = tid >> 5;
    int l = tid & 31;
    int g = g0 + l;
    int b  = g / HWn;
    int hw = g - b*HWn;

    const float* t2r = t2_s + l*65;
    float lg[32];
    float lmax = -3.4e38f; int lamax = 0;
    #pragma unroll
    for (int j = 0; j < 32; j++) {
        int oc = w*32 + j;
        float acc = b3_s[oc];
        const float4* wrow = (const float4*)(w3_s + oc*64);
        #pragma unroll
        for (int k4 = 0; k4 < 16; k4++) {
            float4 wv = wrow[k4];
            acc = fmaf(t2r[k4*4+0], wv.x, acc);
            acc = fmaf(t2r[k4*4+1], wv.y, acc);
            acc = fmaf(t2r[k4*4+2], wv.z, acc);
            acc = fmaf(t2r[k4*4+3], wv.w, acc);
        }
        lg[j] = acc;
        if (acc > lmax) { lmax = acc; lamax = oc; }
    }

    redA[w*33 + l] = lmax; redI[w*33 + l] = lamax;
    __syncthreads();
    float M = -3.4e38f; int A = 0;
    #pragma unroll
    for (int ww = 0; ww < 8; ww++) {
        float m = redA[ww*33 + l];
        if (m > M) { M = m; A = redI[ww*33 + l]; }
    }

    float s = 0.f;
    #pragma unroll
    for (int j = 0; j < 32; j++) { lg[j] = __expf(lg[j] - M); s += lg[j]; }
    __syncthreads();
    redA[w*33 + l] = s;
    __syncthreads();
    float S = 0.f;
    #pragma unroll
    for (int ww = 0; ww < 8; ww++) S += redA[ww*33 + l];
    float rS = 1.f / S;

    int lo = A - 4, hi = A + 4;
    int ocl = lo < 0 ? 0 : lo;
    int och = hi > 255 ? 255 : hi;
    float num = 0.f, den = 0.f;
    #pragma unroll
    for (int j = 0; j < 32; j++) {
        int oc = w*32 + j;
        if (oc >= ocl && oc <= och) {
            float mult = 1.f;
            if (oc == 0   && lo < 0)   mult += (float)(-lo);
            if (oc == 255 && hi > 255) mult += (float)(hi - 255);
            float pv = lg[j] * rS;
            num = fmaf(mult * (float)oc, pv, num);
            den = fmaf(mult, pv, den);
        }
    }
    __syncthreads();
    redA[w*33 + l] = num; redB[w*33 + l] = den;
    __syncthreads();
    if (w == 0) {
        float Nv = 0.f, D = 0.f;
        #pragma unroll
        for (int ww = 0; ww < 8; ww++) { Nv += redA[ww*33 + l]; D += redB[ww*33 + l]; }
        nd[g] = (Nv / (1e-6f + D)) * (1.0f / 255.0f);
    }

    float* pbase = prob + (size_t)b*NSn*HWn + hw;
    #pragma unroll
    for (int j = 0; j < 32; j++)
        pbase[(size_t)(w*32 + j)*HWn] = lg[j] * rS;
}

// ---------------- launch ------------------------------------------------------
extern "C" void kernel_launch(void* const* d_in, const int* in_sizes, int n_in,
                              void* d_out, int out_size)
{
    const float* hidden  = (const float*)d_in[0];
    const float* ndep    = (const float*)d_in[1];
    const float* corr    = (const float*)d_in[2];
    const float* convz_w = (const float*)d_in[3];
    const float* convz_b = (const float*)d_in[4];
    const float* convr_w = (const float*)d_in[5];
    const float* convr_b = (const float*)d_in[6];
    const float* convq_w = (const float*)d_in[7];
    const float* convq_b = (const float*)d_in[8];
    const float* dh1_w   = (const float*)d_in[9];
    const float* dh2_w   = (const float*)d_in[10];
    const float* dh3_w   = (const float*)d_in[11];
    const float* dh3_b   = (const float*)d_in[12];
    const float* ch1_w   = (const float*)d_in[13];
    const float* ch2_w   = (const float*)d_in[14];
    const float* ch2_b   = (const float*)d_in[15];

    float* out = (float*)d_out;
    float* out_h     = out;
    float* out_nd    = out_h  + (size_t)NPIX*32;
    float* out_prob  = out_nd + NPIX;
    float* out_conf  = out_prob + (size_t)NPIX*256;
    float* out_conf0 = out_conf + NPIX;

    float* zbuf;  cudaGetSymbolAddress((void**)&zbuf,  g_z);
    float* t2buf; cudaGetSymbolAddress((void**)&t2buf, g_t2);

    const int SMEM_M0 = 10*18*336 + 2*64*96;              // 72768
    const int SMEM_M1 = 10*18*336 + 2*32*96;              // 66624
    const int SMEM_M2 = 12*20*144 + 2*64*96 + 8192;       // 55040
    const int SMEM_SMAX = (256*64 + 32*65 + 256 + 3*8*33)*4;

    cudaFuncSetAttribute(conv_mma<0>, cudaFuncAttributeMaxDynamicSharedMemorySize, SMEM_M0);
    cudaFuncSetAttribute(conv_mma<1>, cudaFuncAttributeMaxDynamicSharedMemorySize, SMEM_M1);
    cudaFuncSetAttribute(conv_mma<2>, cudaFuncAttributeMaxDynamicSharedMemorySize, SMEM_M2);
    cudaFuncSetAttribute(softmax_head, cudaFuncAttributeMaxDynamicSharedMemorySize, SMEM_SMAX);

    prep_inputs<<<NPIX/128, 128>>>(hidden, ndep, corr);
    prep_weights<<<(87552 + 255)/256, 256>>>(convz_w, convr_w, convq_w, dh1_w, ch1_w);

    dim3 blk(128);
    dim3 grd(Wn/16, Hn/8, Bn);   // 20 x 32 x 4

    conv_mma<0><<<grd, blk, SMEM_M0>>>(convz_b, convr_b, hidden,
                                       nullptr, nullptr, nullptr,
                                       zbuf, nullptr, nullptr);
    conv_mma<1><<<grd, blk, SMEM_M1>>>(convq_b, nullptr, hidden,
                                       nullptr, nullptr, nullptr,
                                       out_h, nullptr, nullptr);
    conv_mma<2><<<grd, blk, SMEM_M2>>>(nullptr, nullptr, nullptr,
                                       dh2_w, ch2_w, ch2_b,
                                       t2buf, out_conf, out_conf0);
    softmax_head<<<NPIX/32, 256, SMEM_SMAX>>>(t2buf, dh3_w, dh3_b,
                                              out_prob, out_nd);
}